// round 6
// baseline (speedup 1.0000x reference)
#include <cuda_runtime.h>
#include <math.h>

// ---------------- scratch (device globals; allocation-free) ----------------
__device__ float g_h1[16 * 64 * 128 * 128];   // conv1 out
__device__ float g_h2[16 * 128 * 64 * 64];    // conv2 out / ping
__device__ float g_h3[16 * 128 * 64 * 64];    // conv3 out / pong
__device__ float g_t [16 * 32 * 64 * 64];     // residual bottleneck
__device__ float g_en[2048 * 4];              // normalized codebook

// ---------------- f32x2 packed helpers (sm_103a) ----------------
__device__ __forceinline__ unsigned long long fma2(unsigned long long a,
                                                   unsigned long long b,
                                                   unsigned long long c) {
    unsigned long long d;
    asm("fma.rn.f32x2 %0, %1, %2, %3;" : "=l"(d) : "l"(a), "l"(b), "l"(c));
    return d;
}
__device__ __forceinline__ float2 unpack2(unsigned long long v) {
    float2 r;
    asm("mov.b64 {%0, %1}, %2;" : "=f"(r.x), "=f"(r.y) : "l"(v));
    return r;
}

__device__ __forceinline__ constexpr int ilog2(int x) {
    int l = 0;
    while ((1 << l) < x) l++;
    return l;
}

// ---------------- codebook normalization ----------------
__global__ void normalize_codebook_kernel(const float* __restrict__ cb) {
    int k = blockIdx.x * blockDim.x + threadIdx.x;
    if (k < 2048) {
        float x0 = cb[k * 4 + 0];
        float x1 = cb[k * 4 + 1];
        float x2 = cb[k * 4 + 2];
        float x3 = cb[k * 4 + 3];
        float ss = __fadd_rn(__fadd_rn(__fadd_rn(__fmul_rn(x0, x0), __fmul_rn(x1, x1)),
                                       __fmul_rn(x2, x2)), __fmul_rn(x3, x3));
        float den = sqrtf(ss) + 1e-12f;
        g_en[k * 4 + 0] = x0 / den;
        g_en[k * 4 + 1] = x1 / den;
        g_en[k * 4 + 2] = x2 / den;
        g_en[k * 4 + 3] = x3 / den;
    }
}

// ---------------- implicit-GEMM conv, FFMA2, dup-B smem, double-buffered ----
// GEMM view: M = B*HOUT*WOUT pixels, N = COUT, K = CIN*KH*KW.
// Micro-tile 8x8 per thread (4 f32x2 M-pairs x 8 N). B stored duplicated
// {w,w} in smem so the inner loop has ZERO mov.b64 packing.
template<int CIN, int COUT, int KH, int KW, int S, int P,
         int HIN, int WIN, int HOUT, int WOUT,
         int BM, int BN, int NT, int MINB,
         bool RELU_IN, bool RELU_OUT, bool ADD>
__global__ __launch_bounds__(NT, MINB)
void conv_gemm_kernel(const float* __restrict__ in,
                      const float* __restrict__ w,
                      const float* __restrict__ bias,
                      const float* __restrict__ res,
                      float* __restrict__ out) {
    constexpr int K   = CIN * KH * KW;
    constexpr int BK  = 8;
    constexpr int TMG = BM / 8;
    constexpr int TNG = BN / 8;
    static_assert(TMG * TNG == NT, "thread count mismatch");
    constexpr int AE  = BM * BK / NT;     // a elements gathered per thread
    constexpr int NB4 = BN * BK / 4;      // float4 weight loads per tile
    static_assert(NB4 <= NT, "weight load mapping");
    constexpr int KK  = KH * KW;
    constexpr int HW  = HOUT * WOUT;
    constexpr int LOG_HW   = ilog2(HW);
    constexpr int LOG_WOUT = ilog2(WOUT);
    constexpr int LOG_HOUT = ilog2(HOUT);
    constexpr int LOG_BM   = ilog2(BM);
    constexpr int T   = K / BK;
    static_assert(K % BK == 0, "K must be multiple of BK");

    __shared__ __align__(16) float As[2][BK][BM];
    __shared__ __align__(16) float Bs[2][BK][BN * 2];   // duplicated: {w,w} pairs

    const int tid = threadIdx.x;
    const int tn  = tid % TNG;
    const int tm  = tid / TNG;
    const int m0  = blockIdx.x * BM;
    const int n0  = blockIdx.y * BN;

    const bool wload = (NB4 == NT) || (tid < NB4);
    const int  nl    = tid % BN;
    const int  kg    = tid / BN;          // 0..BK/4-1

    unsigned long long acc[4][8];
#pragma unroll
    for (int ip = 0; ip < 4; ip++)
#pragma unroll
        for (int j = 0; j < 8; j++) acc[ip][j] = 0ull;

    float  a_stg[AE];
    float4 w_stg = make_float4(0.f, 0.f, 0.f, 0.f);

    // ---- gather tile k0 into staging regs ----
    auto gather = [&](int k0) {
#pragma unroll
        for (int i = 0; i < AE; i++) {
            const int e   = tid + i * NT;
            const int ml  = e & (BM - 1);
            const int kl  = e >> LOG_BM;
            const int m   = m0 + ml;
            const int ox  = m & (WOUT - 1);
            const int oy  = (m >> LOG_WOUT) & (HOUT - 1);
            const int b   = m >> (LOG_WOUT + LOG_HOUT);
            const int k   = k0 + kl;
            const int cin = k / KK;
            const int r   = k - cin * KK;
            const int kh  = r / KW;
            const int kw  = r - kh * KW;
            const int iy  = oy * S - P + kh;
            const int ix  = ox * S - P + kw;
            float v = 0.0f;
            if ((unsigned)iy < (unsigned)HIN && (unsigned)ix < (unsigned)WIN)
                v = in[b * (CIN * HIN * WIN) + cin * (HIN * WIN) + iy * WIN + ix];
            if (RELU_IN) v = fmaxf(v, 0.0f);
            a_stg[i] = v;
        }
        if (wload)
            w_stg = *reinterpret_cast<const float4*>(
                w + (size_t)(n0 + nl) * K + k0 + kg * 4);
    };

    auto commit = [&](int buf) {
#pragma unroll
        for (int i = 0; i < AE; i++) {
            const int e = tid + i * NT;
            As[buf][e >> LOG_BM][e & (BM - 1)] = a_stg[i];
        }
        if (wload) {
            // duplicated store: each weight written as {w,w}
            *reinterpret_cast<float2*>(&Bs[buf][kg * 4 + 0][nl * 2]) = make_float2(w_stg.x, w_stg.x);
            *reinterpret_cast<float2*>(&Bs[buf][kg * 4 + 1][nl * 2]) = make_float2(w_stg.y, w_stg.y);
            *reinterpret_cast<float2*>(&Bs[buf][kg * 4 + 2][nl * 2]) = make_float2(w_stg.z, w_stg.z);
            *reinterpret_cast<float2*>(&Bs[buf][kg * 4 + 3][nl * 2]) = make_float2(w_stg.w, w_stg.w);
        }
    };

    // ---- prologue ----
    gather(0);
    commit(0);
    if (T > 1) gather(BK);
    __syncthreads();

    // ---- main loop: one sync per tile ----
    for (int t = 0; t < T; t++) {
        if (t + 1 < T) commit((t + 1) & 1);          // staged tile t+1 -> other buffer
        if (t + 2 < T) gather((t + 2) * BK);         // prefetch tile t+2 (overlaps compute)

        const int cur = t & 1;
#pragma unroll
        for (int kk = 0; kk < BK; kk++) {
            const ulonglong2 a01 = *reinterpret_cast<const ulonglong2*>(&As[cur][kk][tm * 8]);
            const ulonglong2 a23 = *reinterpret_cast<const ulonglong2*>(&As[cur][kk][tm * 8 + 4]);
            unsigned long long ap[4] = {a01.x, a01.y, a23.x, a23.y};

            // B already duplicated in smem: 4 x LDS.128 = 8 {w,w} pairs, no MOVs
            const ulonglong2 b01 = *reinterpret_cast<const ulonglong2*>(&Bs[cur][kk][tn * 16 + 0]);
            const ulonglong2 b23 = *reinterpret_cast<const ulonglong2*>(&Bs[cur][kk][tn * 16 + 4]);
            const ulonglong2 b45 = *reinterpret_cast<const ulonglong2*>(&Bs[cur][kk][tn * 16 + 8]);
            const ulonglong2 b67 = *reinterpret_cast<const ulonglong2*>(&Bs[cur][kk][tn * 16 + 12]);
            unsigned long long bd[8] = {b01.x, b01.y, b23.x, b23.y,
                                        b45.x, b45.y, b67.x, b67.y};
#pragma unroll
            for (int ip = 0; ip < 4; ip++)
#pragma unroll
                for (int j = 0; j < 8; j++)
                    acc[ip][j] = fma2(ap[ip], bd[j], acc[ip][j]);
        }
        if (t + 1 < T) __syncthreads();
    }

    // ---- epilogue: 8 contiguous m per (thread, n) -> two STG.128 ----
    const int m_start = m0 + tm * 8;
    const int bb  = m_start >> LOG_HW;
    const int yx  = m_start & (HW - 1);
#pragma unroll
    for (int j = 0; j < 8; j++) {
        const int n = n0 + tn * 8 + j;
        const float bv = bias[n];
        const size_t obase = (((size_t)(bb * COUT + n)) << LOG_HW) + yx;
        float v[8];
#pragma unroll
        for (int ip = 0; ip < 4; ip++) {
            const float2 p = unpack2(acc[ip][j]);
            v[2 * ip]     = p.x + bv;
            v[2 * ip + 1] = p.y + bv;
        }
        if (ADD) {
            const float4 r0 = *reinterpret_cast<const float4*>(res + obase);
            const float4 r1 = *reinterpret_cast<const float4*>(res + obase + 4);
            v[0] += r0.x; v[1] += r0.y; v[2] += r0.z; v[3] += r0.w;
            v[4] += r1.x; v[5] += r1.y; v[6] += r1.z; v[7] += r1.w;
        }
        if (RELU_OUT) {
#pragma unroll
            for (int i = 0; i < 8; i++) v[i] = fmaxf(v[i], 0.0f);
        }
        *reinterpret_cast<float4*>(out + obase)     = make_float4(v[0], v[1], v[2], v[3]);
        *reinterpret_cast<float4*>(out + obase + 4) = make_float4(v[4], v[5], v[6], v[7]);
    }
}

// ---------------- fused wpre (1x1, 128->4) + cosine VQ ----------------
__global__ __launch_bounds__(256)
void vq_kernel(const float* __restrict__ h,
               const float* __restrict__ wpre,   // [4,128]
               const float* __restrict__ bpre,   // [4]
               const float* __restrict__ cb,     // [2048,4]
               float* __restrict__ out) {
    __shared__ float4 en_s[2048];
    __shared__ float  wp[128][4];
    __shared__ float  bp[4];

    const int tid = threadIdx.x;
    const float4* en4 = reinterpret_cast<const float4*>(g_en);
#pragma unroll
    for (int i = tid; i < 2048; i += 256) en_s[i] = en4[i];
    for (int i = tid; i < 512; i += 256) {
        const int d = i >> 7;
        const int c = i & 127;
        wp[c][d] = wpre[i];
    }
    if (tid < 4) bp[tid] = bpre[tid];
    __syncthreads();

    const int pix = blockIdx.x * 256 + tid;
    const int b   = pix >> 12;
    const int yx  = pix & 4095;
    const float* hb = h + (size_t)b * 128 * 4096 + yx;

    float z0 = bp[0], z1 = bp[1], z2 = bp[2], z3 = bp[3];
#pragma unroll 8
    for (int c = 0; c < 128; c++) {
        const float v = fmaxf(hb[c * 4096], 0.0f);
        z0 = fmaf(wp[c][0], v, z0);
        z1 = fmaf(wp[c][1], v, z1);
        z2 = fmaf(wp[c][2], v, z2);
        z3 = fmaf(wp[c][3], v, z3);
    }

    float best = -INFINITY;
    int   bi   = 0;
#pragma unroll 4
    for (int k = 0; k < 2048; k++) {
        const float4 e = en_s[k];
        const float s = fmaf(z3, e.w, fmaf(z2, e.z, fmaf(z1, e.y, __fmul_rn(z0, e.x))));
        if (s > best) { best = s; bi = k; }   // strict > : first-index tie-break
    }

    const float4 q = reinterpret_cast<const float4*>(cb)[bi];
    out[(b * 4 + 0) * 4096 + yx] = q.x;
    out[(b * 4 + 1) * 4096 + yx] = q.y;
    out[(b * 4 + 2) * 4096 + yx] = q.z;
    out[(b * 4 + 3) * 4096 + yx] = q.w;
}

// ---------------- launch ----------------
extern "C" void kernel_launch(void* const* d_in, const int* in_sizes, int n_in,
                              void* d_out, int out_size) {
    const float* cond = (const float*)d_in[0];
    const float* w1   = (const float*)d_in[1];
    const float* b1   = (const float*)d_in[2];
    const float* w2   = (const float*)d_in[3];
    const float* b2   = (const float*)d_in[4];
    const float* w3   = (const float*)d_in[5];
    const float* b3   = (const float*)d_in[6];
    const float* r1w1 = (const float*)d_in[7];
    const float* r1b1 = (const float*)d_in[8];
    const float* r1w2 = (const float*)d_in[9];
    const float* r1b2 = (const float*)d_in[10];
    const float* r2w1 = (const float*)d_in[11];
    const float* r2b1 = (const float*)d_in[12];
    const float* r2w2 = (const float*)d_in[13];
    const float* r2b2 = (const float*)d_in[14];
    const float* wpre = (const float*)d_in[15];
    const float* bpre = (const float*)d_in[16];
    const float* cb   = (const float*)d_in[17];
    float* out = (float*)d_out;

    float *h1, *h2, *h3, *t;
    cudaGetSymbolAddress((void**)&h1, g_h1);
    cudaGetSymbolAddress((void**)&h2, g_h2);
    cudaGetSymbolAddress((void**)&h3, g_h3);
    cudaGetSymbolAddress((void**)&t,  g_t);

    normalize_codebook_kernel<<<8, 256>>>(cb);

    // conv1: [16,1,256,256] -> relu -> [16,64,128,128]   (M=262144, K=16, N=64)
    conv_gemm_kernel<1, 64, 4, 4, 2, 1, 256, 256, 128, 128, 256, 64, 256, 2, false, true, false>
        <<<dim3(262144 / 256, 1), 256>>>(cond, w1, b1, nullptr, h1);

    // conv2: -> relu -> [16,128,64,64]                    (M=65536, K=1024, N=128)
    conv_gemm_kernel<64, 128, 4, 4, 2, 1, 128, 128, 64, 64, 128, 128, 256, 2, false, true, false>
        <<<dim3(65536 / 128, 1), 256>>>(h1, w2, b2, nullptr, h2);

    // conv3: -> [16,128,64,64]                            (M=65536, K=1152, N=128)
    conv_gemm_kernel<128, 128, 3, 3, 1, 1, 64, 64, 64, 64, 128, 128, 256, 2, false, false, false>
        <<<dim3(65536 / 128, 1), 256>>>(h2, w3, b3, nullptr, h3);

    // res block 1: t = conv3x3(relu(h3)); h2 = h3 + conv1x1(relu(t))
    conv_gemm_kernel<128, 32, 3, 3, 1, 1, 64, 64, 64, 64, 256, 32, 128, 4, true, false, false>
        <<<dim3(65536 / 256, 1), 128>>>(h3, r1w1, r1b1, nullptr, t);
    conv_gemm_kernel<32, 128, 1, 1, 1, 0, 64, 64, 64, 64, 128, 128, 256, 2, true, false, true>
        <<<dim3(65536 / 128, 1), 256>>>(t, r1w2, r1b2, h3, h2);

    // res block 2: t = conv3x3(relu(h2)); h3 = h2 + conv1x1(relu(t))
    conv_gemm_kernel<128, 32, 3, 3, 1, 1, 64, 64, 64, 64, 256, 32, 128, 4, true, false, false>
        <<<dim3(65536 / 256, 1), 128>>>(h2, r2w1, r2b1, nullptr, t);
    conv_gemm_kernel<32, 128, 1, 1, 1, 0, 64, 64, 64, 64, 128, 128, 256, 2, true, false, true>
        <<<dim3(65536 / 128, 1), 256>>>(t, r2w2, r2b2, h2, h3);

    // fused relu + wpre + VQ
    vq_kernel<<<16 * 64 * 64 / 256, 256>>>(h3, wpre, bpre, cb, out);
}

// round 13
// speedup vs baseline: 2.1400x; 2.1400x over previous
#include <cuda_runtime.h>
#include <math.h>

// ---------------- scratch (device globals; allocation-free) ----------------
__device__ float g_h1[16 * 64 * 128 * 128];   // conv1 out
__device__ float g_h2[16 * 128 * 64 * 64];    // conv2 out / ping
__device__ float g_h3[16 * 128 * 64 * 64];    // conv3 out / pong
__device__ float g_t [16 * 32 * 64 * 64];     // residual bottleneck
__device__ float g_en[2048 * 4];              // normalized codebook

// ---------------- f32x2 packed helpers (sm_103a) ----------------
__device__ __forceinline__ unsigned long long fma2(unsigned long long a,
                                                   unsigned long long b,
                                                   unsigned long long c) {
    unsigned long long d;
    asm("fma.rn.f32x2 %0, %1, %2, %3;" : "=l"(d) : "l"(a), "l"(b), "l"(c));
    return d;
}
__device__ __forceinline__ unsigned long long dup2(float x) {
    unsigned long long d;
    asm("mov.b64 %0, {%1, %1};" : "=l"(d) : "f"(x));
    return d;
}
__device__ __forceinline__ float2 unpack2(unsigned long long v) {
    float2 r;
    asm("mov.b64 {%0, %1}, %2;" : "=f"(r.x), "=f"(r.y) : "l"(v));
    return r;
}

__device__ __forceinline__ constexpr int ilog2(int x) {
    int l = 0;
    while ((1 << l) < x) l++;
    return l;
}

// ---------------- codebook normalization ----------------
__global__ void normalize_codebook_kernel(const float* __restrict__ cb) {
    int k = blockIdx.x * blockDim.x + threadIdx.x;
    if (k < 2048) {
        float x0 = cb[k * 4 + 0];
        float x1 = cb[k * 4 + 1];
        float x2 = cb[k * 4 + 2];
        float x3 = cb[k * 4 + 3];
        float ss = __fadd_rn(__fadd_rn(__fadd_rn(__fmul_rn(x0, x0), __fmul_rn(x1, x1)),
                                       __fmul_rn(x2, x2)), __fmul_rn(x3, x3));
        float den = sqrtf(ss) + 1e-12f;
        g_en[k * 4 + 0] = x0 / den;
        g_en[k * 4 + 1] = x1 / den;
        g_en[k * 4 + 2] = x2 / den;
        g_en[k * 4 + 3] = x3 / den;
    }
}

// ---------------- implicit-GEMM conv, FFMA2, double-buffered ----------------
// GEMM view: M = B*HOUT*WOUT pixels, N = COUT, K = CIN*KH*KW.
// Micro-tile: MPACK M-values (MPACK/2 f32x2 pairs) x TN N-values per thread.
template<int CIN, int COUT, int KH, int KW, int S, int P,
         int HIN, int WIN, int HOUT, int WOUT,
         int BM, int BN, int MPACK, int TN, int MINB,
         bool RELU_IN, bool RELU_OUT, bool ADD>
__global__ __launch_bounds__((BM / MPACK) * (BN / TN), MINB)
void conv_gemm_kernel(const float* __restrict__ in,
                      const float* __restrict__ w,
                      const float* __restrict__ bias,
                      const float* __restrict__ res,
                      float* __restrict__ out) {
    constexpr int K     = CIN * KH * KW;
    constexpr int BK    = 8;
    constexpr int TMG   = BM / MPACK;
    constexpr int TNG   = BN / TN;
    constexpr int NT    = TMG * TNG;
    constexpr int NPAIR = MPACK / 2;
    constexpr int AE    = BM * BK / NT;    // A elements gathered per thread
    constexpr int NB4   = BN * BK / 4;     // float4 weight loads per tile
    static_assert(NB4 <= NT, "weight load mapping");
    constexpr int KK  = KH * KW;
    constexpr int HW  = HOUT * WOUT;
    constexpr int LOG_HW   = ilog2(HW);
    constexpr int LOG_WOUT = ilog2(WOUT);
    constexpr int LOG_HOUT = ilog2(HOUT);
    constexpr int LOG_BM   = ilog2(BM);
    constexpr int T   = K / BK;
    static_assert(K % BK == 0, "K must be multiple of BK");
    static_assert(HW % MPACK == 0, "no batch straddle");

    __shared__ __align__(16) float As[2][BK][BM];
    __shared__ __align__(16) float Bs[2][BK][BN];

    const int tid = threadIdx.x;
    const int tn  = tid % TNG;
    const int tm  = tid / TNG;
    const int m0  = blockIdx.x * BM;
    const int n0  = blockIdx.y * BN;

    const bool wload = (NB4 == NT) || (tid < NB4);
    const int  nl    = tid % BN;
    const int  kg    = tid / BN;

    unsigned long long acc[NPAIR][TN];
#pragma unroll
    for (int ip = 0; ip < NPAIR; ip++)
#pragma unroll
        for (int j = 0; j < TN; j++) acc[ip][j] = 0ull;

    float  a_stg[AE];
    float4 w_stg = make_float4(0.f, 0.f, 0.f, 0.f);

    auto gather = [&](int k0) {
#pragma unroll
        for (int i = 0; i < AE; i++) {
            const int e   = tid + i * NT;
            const int ml  = e & (BM - 1);
            const int kl  = e >> LOG_BM;
            const int m   = m0 + ml;
            const int ox  = m & (WOUT - 1);
            const int oy  = (m >> LOG_WOUT) & (HOUT - 1);
            const int b   = m >> (LOG_WOUT + LOG_HOUT);
            const int k   = k0 + kl;
            const int cin = k / KK;
            const int r   = k - cin * KK;
            const int kh  = r / KW;
            const int kw  = r - kh * KW;
            const int iy  = oy * S - P + kh;
            const int ix  = ox * S - P + kw;
            float v = 0.0f;
            if ((unsigned)iy < (unsigned)HIN && (unsigned)ix < (unsigned)WIN)
                v = in[b * (CIN * HIN * WIN) + cin * (HIN * WIN) + iy * WIN + ix];
            if (RELU_IN) v = fmaxf(v, 0.0f);
            a_stg[i] = v;
        }
        if (wload)
            w_stg = *reinterpret_cast<const float4*>(
                w + (size_t)(n0 + nl) * K + k0 + kg * 4);
    };

    auto commit = [&](int buf) {
#pragma unroll
        for (int i = 0; i < AE; i++) {
            const int e = tid + i * NT;
            As[buf][e >> LOG_BM][e & (BM - 1)] = a_stg[i];
        }
        if (wload) {
            Bs[buf][kg * 4 + 0][nl] = w_stg.x;
            Bs[buf][kg * 4 + 1][nl] = w_stg.y;
            Bs[buf][kg * 4 + 2][nl] = w_stg.z;
            Bs[buf][kg * 4 + 3][nl] = w_stg.w;
        }
    };

    // ---- prologue ----
    gather(0);
    commit(0);
    if (T > 1) gather(BK);
    __syncthreads();

    // ---- main loop: one sync per tile ----
    for (int t = 0; t < T; t++) {
        if (t + 1 < T) commit((t + 1) & 1);
        if (t + 2 < T) gather((t + 2) * BK);

        const int cur = t & 1;
#pragma unroll
        for (int kk = 0; kk < BK; kk++) {
            unsigned long long ap[NPAIR];
#pragma unroll
            for (int i = 0; i < NPAIR / 2; i++) {
                // each ulonglong2 = 4 floats -> advance by 4 per iteration
                const ulonglong2 t2 = *reinterpret_cast<const ulonglong2*>(
                    &As[cur][kk][tm * MPACK + 4 * i]);
                ap[2 * i]     = t2.x;
                ap[2 * i + 1] = t2.y;
            }

            float bsv[TN];
            if (TN == 4) {
                const float4 b4 = *reinterpret_cast<const float4*>(&Bs[cur][kk][tn * 4]);
                bsv[0] = b4.x; bsv[1] = b4.y; bsv[2] = b4.z; bsv[3] = b4.w;
            } else if (TN == 2) {
                const float2 b2 = *reinterpret_cast<const float2*>(&Bs[cur][kk][tn * 2]);
                bsv[0] = b2.x; bsv[1] = b2.y;
            } else {
#pragma unroll
                for (int j = 0; j < TN; j++) bsv[j] = Bs[cur][kk][tn * TN + j];
            }
            unsigned long long bd[TN];
#pragma unroll
            for (int j = 0; j < TN; j++) bd[j] = dup2(bsv[j]);

#pragma unroll
            for (int ip = 0; ip < NPAIR; ip++)
#pragma unroll
                for (int j = 0; j < TN; j++)
                    acc[ip][j] = fma2(ap[ip], bd[j], acc[ip][j]);
        }
        if (t + 1 < T) __syncthreads();
    }

    // ---- epilogue: MPACK contiguous m per (thread, n) -> STG.128 chunks ----
    const int m_start = m0 + tm * MPACK;
    const int bb  = m_start >> LOG_HW;
    const int yx  = m_start & (HW - 1);
#pragma unroll
    for (int j = 0; j < TN; j++) {
        const int n = n0 + tn * TN + j;
        const float bv = bias[n];
        const size_t obase = (((size_t)(bb * COUT + n)) << LOG_HW) + yx;
        float v[MPACK];
#pragma unroll
        for (int ip = 0; ip < NPAIR; ip++) {
            const float2 p = unpack2(acc[ip][j]);
            v[2 * ip]     = p.x + bv;
            v[2 * ip + 1] = p.y + bv;
        }
        if (ADD) {
#pragma unroll
            for (int c = 0; c < MPACK / 4; c++) {
                const float4 r4 = *reinterpret_cast<const float4*>(res + obase + 4 * c);
                v[4 * c + 0] += r4.x; v[4 * c + 1] += r4.y;
                v[4 * c + 2] += r4.z; v[4 * c + 3] += r4.w;
            }
        }
        if (RELU_OUT) {
#pragma unroll
            for (int i = 0; i < MPACK; i++) v[i] = fmaxf(v[i], 0.0f);
        }
#pragma unroll
        for (int c = 0; c < MPACK / 4; c++)
            *reinterpret_cast<float4*>(out + obase + 4 * c) =
                make_float4(v[4 * c + 0], v[4 * c + 1], v[4 * c + 2], v[4 * c + 3]);
    }
}

// ---------------- fused wpre (1x1, 128->4) + cosine VQ ----------------
__global__ __launch_bounds__(256)
void vq_kernel(const float* __restrict__ h,
               const float* __restrict__ wpre,   // [4,128]
               const float* __restrict__ bpre,   // [4]
               const float* __restrict__ cb,     // [2048,4]
               float* __restrict__ out) {
    __shared__ float4 en_s[2048];
    __shared__ float  wp[128][4];
    __shared__ float  bp[4];

    const int tid = threadIdx.x;
    const float4* en4 = reinterpret_cast<const float4*>(g_en);
#pragma unroll
    for (int i = tid; i < 2048; i += 256) en_s[i] = en4[i];
    for (int i = tid; i < 512; i += 256) {
        const int d = i >> 7;
        const int c = i & 127;
        wp[c][d] = wpre[i];
    }
    if (tid < 4) bp[tid] = bpre[tid];
    __syncthreads();

    const int pix = blockIdx.x * 256 + tid;
    const int b   = pix >> 12;
    const int yx  = pix & 4095;
    const float* hb = h + (size_t)b * 128 * 4096 + yx;

    float z0 = bp[0], z1 = bp[1], z2 = bp[2], z3 = bp[3];
#pragma unroll 8
    for (int c = 0; c < 128; c++) {
        const float v = fmaxf(hb[c * 4096], 0.0f);
        z0 = fmaf(wp[c][0], v, z0);
        z1 = fmaf(wp[c][1], v, z1);
        z2 = fmaf(wp[c][2], v, z2);
        z3 = fmaf(wp[c][3], v, z3);
    }

    float best = -INFINITY;
    int   bi   = 0;
#pragma unroll 4
    for (int k = 0; k < 2048; k++) {
        const float4 e = en_s[k];
        const float s = fmaf(z3, e.w, fmaf(z2, e.z, fmaf(z1, e.y, __fmul_rn(z0, e.x))));
        if (s > best) { best = s; bi = k; }   // strict > : first-index tie-break
    }

    const float4 q = reinterpret_cast<const float4*>(cb)[bi];
    out[(b * 4 + 0) * 4096 + yx] = q.x;
    out[(b * 4 + 1) * 4096 + yx] = q.y;
    out[(b * 4 + 2) * 4096 + yx] = q.z;
    out[(b * 4 + 3) * 4096 + yx] = q.w;
}

// ---------------- launch ----------------
extern "C" void kernel_launch(void* const* d_in, const int* in_sizes, int n_in,
                              void* d_out, int out_size) {
    const float* cond = (const float*)d_in[0];
    const float* w1   = (const float*)d_in[1];
    const float* b1   = (const float*)d_in[2];
    const float* w2   = (const float*)d_in[3];
    const float* b2   = (const float*)d_in[4];
    const float* w3   = (const float*)d_in[5];
    const float* b3   = (const float*)d_in[6];
    const float* r1w1 = (const float*)d_in[7];
    const float* r1b1 = (const float*)d_in[8];
    const float* r1w2 = (const float*)d_in[9];
    const float* r1b2 = (const float*)d_in[10];
    const float* r2w1 = (const float*)d_in[11];
    const float* r2b1 = (const float*)d_in[12];
    const float* r2w2 = (const float*)d_in[13];
    const float* r2b2 = (const float*)d_in[14];
    const float* wpre = (const float*)d_in[15];
    const float* bpre = (const float*)d_in[16];
    const float* cb   = (const float*)d_in[17];
    float* out = (float*)d_out;

    float *h1, *h2, *h3, *t;
    cudaGetSymbolAddress((void**)&h1, g_h1);
    cudaGetSymbolAddress((void**)&h2, g_h2);
    cudaGetSymbolAddress((void**)&h3, g_h3);
    cudaGetSymbolAddress((void**)&t,  g_t);

    normalize_codebook_kernel<<<8, 256>>>(cb);

    // conv1: [16,1,256,256] -> relu -> [16,64,128,128]   (M=262144, K=16, N=64)
    // MPACK=8, TN=4 (R2-proven shape), 256 thr
    conv_gemm_kernel<1, 64, 4, 4, 2, 1, 256, 256, 128, 128, 128, 64, 8, 4, 2, false, true, false>
        <<<dim3(262144 / 128, 1), 256>>>(cond, w1, b1, nullptr, h1);

    // conv2: -> relu -> [16,128,64,64]   (M=65536, K=1024, N=128)  MPACK=16, TN=4
    conv_gemm_kernel<64, 128, 4, 4, 2, 1, 128, 128, 64, 64, 128, 128, 16, 4, 2, false, true, false>
        <<<dim3(65536 / 128, 1), 256>>>(h1, w2, b2, nullptr, h2);

    // conv3: -> [16,128,64,64]           (M=65536, K=1152, N=128)  MPACK=16, TN=4
    conv_gemm_kernel<128, 128, 3, 3, 1, 1, 64, 64, 64, 64, 128, 128, 16, 4, 2, false, false, false>
        <<<dim3(65536 / 128, 1), 256>>>(h2, w3, b3, nullptr, h3);

    // res block 1: t = conv3x3(relu(h3)); h2 = h3 + conv1x1(relu(t))
    // res3x3: MPACK=8, TN=2 (R2-proven shape), 256 thr
    conv_gemm_kernel<128, 32, 3, 3, 1, 1, 64, 64, 64, 64, 128, 32, 8, 2, 2, true, false, false>
        <<<dim3(65536 / 128, 1), 256>>>(h3, r1w1, r1b1, nullptr, t);
    conv_gemm_kernel<32, 128, 1, 1, 1, 0, 64, 64, 64, 64, 128, 128, 16, 4, 2, true, false, true>
        <<<dim3(65536 / 128, 1), 256>>>(t, r1w2, r1b2, h3, h2);

    // res block 2: t = conv3x3(relu(h2)); h3 = h2 + conv1x1(relu(t))
    conv_gemm_kernel<128, 32, 3, 3, 1, 1, 64, 64, 64, 64, 128, 32, 8, 2, 2, true, false, false>
        <<<dim3(65536 / 128, 1), 256>>>(h2, r2w1, r2b1, nullptr, t);
    conv_gemm_kernel<32, 128, 1, 1, 1, 0, 64, 64, 64, 64, 128, 128, 16, 4, 2, true, false, true>
        <<<dim3(65536 / 128, 1), 256>>>(t, r2w2, r2b2, h2, h3);

    // fused relu + wpre + VQ
    vq_kernel<<<16 * 64 * 64 / 256, 256>>>(h3, wpre, bpre, cb, out);
}